// round 7
// baseline (speedup 1.0000x reference)
#include <cuda_runtime.h>
#include <math.h>

// Problem constants (B, F, S, D) = (16, 2048, 512, 256)
#define BB   16
#define FF   2048
#define SS   512
#define DD   256
#define D2   512    // 2*D (hidden width of edge MLP, width of H rows)
#define DLAT 512

#define NEDGE (BB*FF)
#define MAXM  40      // per-(b,node) message bin capacity (mean 6.8)

typedef unsigned long long ull;

// ---------------- scratch (device globals; no allocation allowed) ----------
__device__ float g_NA[SS*D2];     // nodes @ W1[0:256]        (1 MB)
__device__ float g_NC[SS*D2];     // nodes @ W1[512:768]      (1 MB)
__device__ float g_PP[8*D2];      // pred_emb @ W1[256:512] + b1
__device__ float g_RC[8*D2];      // role_emb @ W1[512:768]
__device__ float g_W2q[D2*DD];    // W2 repacked: [k/4][d][k%4]  (512 KB)
__device__ float g_H [BB*SS*D2];  // segment-summed gelu(pre) (16 MB)
__device__ float g_cnt[BB*SS];    // message counts per (b,node)
__device__ int   g_binCnt[BB*SS];         // message counters
__device__ unsigned g_binBuf[BB*SS*MAXM]; // message descriptors (1.3 MB)
__device__ float g_pool[BB*DD];   // sum over S of layernormed x
__device__ float g_L1raw[BB*DLAT];// split-K partial sums of pooled@Wl1
__device__ float g_L1[BB*DLAT];   // gelu(pooled@Wl1+bl1)

__device__ __forceinline__ float gelu_f(float x) {
    return 0.5f * x * (1.0f + erff(x * 0.70710678118654752f));
}

// packed f32x2 fma: d = a*b + d  (elementwise on the two packed floats)
__device__ __forceinline__ void ffma2(ull& d, ull a, ull b) {
    asm("fma.rn.f32x2 %0, %1, %2, %3;" : "=l"(d) : "l"(a), "l"(b), "l"(d));
}
__device__ __forceinline__ ull pack2(float x, float y) {
    ull r; asm("mov.b64 %0, {%1, %2};" : "=l"(r) : "f"(x), "f"(y)); return r;
}
__device__ __forceinline__ float2 unpack2(ull v) {
    float2 r; asm("mov.b64 {%0, %1}, %2;" : "=f"(r.x), "=f"(r.y) : "l"(v)); return r;
}
// 128-bit vector reduction (sm_90+)
__device__ __forceinline__ void red_add_v4(float* addr, float4 v) {
    asm volatile("red.global.add.v4.f32 [%0], {%1, %2, %3, %4};"
                 :: "l"(addr), "f"(v.x), "f"(v.y), "f"(v.z), "f"(v.w) : "memory");
}

// ---------------- 1: merged prep kernel ------------------------------------
// grid = 512 blocks x 256 threads; block roles:
//   [0,64):    NA/NC precompute (8 node rows each, f32x2)
//   [64,80):   PP (rows 0-7) / RC (rows 8-15)
//   [80,96):   W2q repack
//   [96,512):  zero g_H, g_binCnt, g_pool, g_L1raw
__global__ __launch_bounds__(256) void prep_kernel(
    const float* __restrict__ pos_emb, const float* __restrict__ pred_emb,
    const float* __restrict__ role_emb, const float* __restrict__ W1,
    const float* __restrict__ b1, const float* __restrict__ W2)
{
    __shared__ float sh[8*DD];
    int bid = blockIdx.x;
    int tid = threadIdx.x;

    if (bid < 64) {
        // ---- NA = nodes@W1a, NC = nodes@W1c, rows [bid*8, bid*8+8) ----
        int r0 = bid * 8;
        #pragma unroll
        for (int r = 0; r < 8; r++)
            sh[r*DD + tid] = pos_emb[(r0 + r)*DD + tid];
        __syncthreads();

        ull aA[8], aC[8];
        #pragma unroll
        for (int r = 0; r < 8; r++) { aA[r] = 0ull; aC[r] = 0ull; }
        int j2 = 2*tid;   // column pair (2*tid, 2*tid+1)
        #pragma unroll 2
        for (int k = 0; k < DD; k++) {
            ull wa = *reinterpret_cast<const ull*>(W1 + (size_t)k*D2 + j2);
            ull wc = *reinterpret_cast<const ull*>(W1 + (size_t)(512 + k)*D2 + j2);
            #pragma unroll
            for (int r = 0; r < 8; r++) {
                float h = sh[r*DD + k];
                ull hp = pack2(h, h);
                ffma2(aA[r], hp, wa);
                ffma2(aC[r], hp, wc);
            }
        }
        #pragma unroll
        for (int r = 0; r < 8; r++) {
            *reinterpret_cast<ull*>(g_NA + (r0+r)*D2 + j2) = aA[r];
            *reinterpret_cast<ull*>(g_NC + (r0+r)*D2 + j2) = aC[r];
        }
    } else if (bid < 80) {
        // ---- PP = pred_emb@W1p + b1 (rows 0-7), RC = role_emb@W1c (8-15) ----
        int row = bid - 64;
        bool is_pred = (row < 8);
        const float* src = is_pred ? (pred_emb + row*DD) : (role_emb + (row-8)*DD);
        sh[tid] = src[tid];
        __syncthreads();

        const float* Wbase = is_pred ? (W1 + 256*D2) : (W1 + 512*D2);
        ull acc = 0ull;
        int j2 = 2*tid;
        #pragma unroll 4
        for (int k = 0; k < DD; k++) {
            ull w = *reinterpret_cast<const ull*>(Wbase + (size_t)k*D2 + j2);
            float s = sh[k];
            ffma2(acc, pack2(s, s), w);
        }
        float2 a = unpack2(acc);
        if (is_pred) {
            g_PP[row*D2 + j2    ] = a.x + b1[j2];
            g_PP[row*D2 + j2 + 1] = a.y + b1[j2+1];
        } else {
            g_RC[(row-8)*D2 + j2    ] = a.x;
            g_RC[(row-8)*D2 + j2 + 1] = a.y;
        }
    } else if (bid < 96) {
        // ---- repack W2 -> W2q[k4*1024 + d*4 + kk] = W2[(k4*4+kk)*DD + d] ----
        for (int i = (bid - 80)*256 + tid; i < D2*DD; i += 16*256) {
            int k4  = i >> 10;
            int rem = i & 1023;
            int d   = rem >> 2;
            int kk  = rem & 3;
            g_W2q[i] = W2[(k4*4 + kk)*DD + d];
        }
    } else {
        // ---- zero accumulators ----
        int idx    = (bid - 96)*256 + tid;
        int stride = (512 - 96)*256;
        float4 z = make_float4(0.f, 0.f, 0.f, 0.f);
        for (int i = idx; i < (BB*SS*D2)/4; i += stride) reinterpret_cast<float4*>(g_H)[i]      = z;
        for (int i = idx; i < (BB*SS)/4;    i += stride) reinterpret_cast<int4*>(g_binCnt)[i]   = make_int4(0,0,0,0);
        for (int i = idx; i < (BB*DD)/4;    i += stride) reinterpret_cast<float4*>(g_pool)[i]   = z;
        for (int i = idx; i < (BB*DLAT)/4;  i += stride) reinterpret_cast<float4*>(g_L1raw)[i]  = z;
    }
}

// ---------------- 2a: bin kernel -------------------------------------------
// one thread per edge: push message descriptors (edge*2 + kind) into the
// destination node's bin. Overflow (never in practice) -> direct global RED.
__global__ __launch_bounds__(256) void bin_kernel(
    const int* __restrict__ a0, const int* __restrict__ a1,
    const int* __restrict__ pred, const int* __restrict__ role)
{
    int e = blockIdx.x * 256 + threadIdx.x;
    if (e >= NEDGE) return;
    int b  = e >> 11;
    int i0 = __ldg(&a0[e]);
    int i1 = __ldg(&a1[e]);
    int p  = __ldg(&pred[e]);
    bool is_role = (p == 1);
    bool do_bwd  = (p >= 2);

    // forward message -> dst
    int dst = is_role ? i0 : i1;
    int binF = b*SS + dst;
    int slotF = atomicAdd(&g_binCnt[binF], 1);
    if (slotF < MAXM) {
        g_binBuf[binF*MAXM + slotF] = (unsigned)(e*2 + 0);
    } else {
        // fallback: compute + RED the whole row (statistically unreachable)
        const float* na0 = g_NA + i0*D2;
        const float* pp  = g_PP + p *D2;
        const float* th  = is_role ? (g_RC + (__ldg(&role[e]) + 1)*D2) : (g_NC + i1*D2);
        float* Hf = g_H + (size_t)binF*D2;
        for (int j = 0; j < D2; j++)
            atomicAdd(&Hf[j], gelu_f(na0[j] + pp[j] + th[j]));
    }
    // backward message -> i0
    if (do_bwd) {
        int binB = b*SS + i0;
        int slotB = atomicAdd(&g_binCnt[binB], 1);
        if (slotB < MAXM) {
            g_binBuf[binB*MAXM + slotB] = (unsigned)(e*2 + 1);
        } else {
            const float* na1 = g_NA + i1*D2;
            const float* pp  = g_PP + p *D2;
            const float* nc0 = g_NC + i0*D2;
            float* Hb = g_H + (size_t)binB*D2;
            for (int j = 0; j < D2; j++)
                atomicAdd(&Hb[j], gelu_f(na1[j] + pp[j] + nc0[j]));
        }
    }
}

// ---------------- 2b: accum kernel -----------------------------------------
// one block of 128 threads per (b, node); replay messages, accumulate in
// registers, write H once (plain store -- this block exclusively owns the row).
__global__ __launch_bounds__(128) void accum_kernel(
    const int* __restrict__ a0, const int* __restrict__ a1,
    const int* __restrict__ pred, const int* __restrict__ role)
{
    int bn  = blockIdx.x;            // b*SS + n
    int j   = threadIdx.x;           // 0..127 -> floats 4j..4j+3
    int cnt = g_binCnt[bn];
    int m   = cnt < MAXM ? cnt : MAXM;

    // start from existing H (zeros, or overflow-fallback contributions)
    float4 acc = reinterpret_cast<const float4*>(g_H + (size_t)bn*D2)[j];

    const unsigned* buf = g_binBuf + (size_t)bn*MAXM;
    for (int s = 0; s < m; s++) {
        unsigned code = __ldg(&buf[s]);
        int  e   = (int)(code >> 1);
        bool bwd = (code & 1u);
        int i0 = __ldg(&a0[e]);
        int i1 = __ldg(&a1[e]);
        int p  = __ldg(&pred[e]);

        const float4* ra;
        const float4* rt;
        const float4* rp = reinterpret_cast<const float4*>(g_PP + p*D2);
        if (!bwd) {
            ra = reinterpret_cast<const float4*>(g_NA + i0*D2);
            rt = (p == 1)
                ? reinterpret_cast<const float4*>(g_RC + (__ldg(&role[e]) + 1)*D2)
                : reinterpret_cast<const float4*>(g_NC + i1*D2);
        } else {
            ra = reinterpret_cast<const float4*>(g_NA + i1*D2);
            rt = reinterpret_cast<const float4*>(g_NC + i0*D2);
        }
        float4 va = ra[j];
        float4 vp = rp[j];
        float4 vt = rt[j];
        acc.x += gelu_f(va.x + vp.x + vt.x);
        acc.y += gelu_f(va.y + vp.y + vt.y);
        acc.z += gelu_f(va.z + vp.z + vt.z);
        acc.w += gelu_f(va.w + vp.w + vt.w);
    }
    reinterpret_cast<float4*>(g_H + (size_t)bn*D2)[j] = acc;
    if (j == 0) g_cnt[bn] = (float)cnt;
}

// ---------------- 3: node kernel: agg = H@W2 + cnt*b2; x = nodes+agg; ------
//                     layernorm; accumulate pooled sum.  f32x2 GEMM.
// grid (SS/16, BB) blocks, 256 threads; 16 nodes per block, thread = column d
__global__ __launch_bounds__(256) void node_kernel(
    const float* __restrict__ pos_emb, const float* __restrict__ b2,
    const float* __restrict__ ln_g, const float* __restrict__ ln_b)
{
    __shared__ float sbuf[16 * D2];   // 32 KB: phase1 = H tile, phase2 = x rows
    __shared__ float scnt[16];

    int b  = blockIdx.y;
    int s0 = blockIdx.x * 16;
    int d  = threadIdx.x;             // 0..255

    // load H tile [16][512] = 2048 float4, 8 per thread
    {
        const float4* Hv = reinterpret_cast<const float4*>(g_H + (size_t)(b*SS + s0)*D2);
        float4* sv = reinterpret_cast<float4*>(sbuf);
        #pragma unroll
        for (int i = 0; i < 8; i++) sv[d + i*256] = Hv[d + i*256];
    }
    if (d < 16) scnt[d] = g_cnt[b*SS + s0 + d];
    __syncthreads();

    // agg[r][d] = sum_k H[r][k] * W2[k][d], packed over (k even, k odd)
    ull acc[16];
    #pragma unroll
    for (int r = 0; r < 16; r++) acc[r] = 0ull;

    #pragma unroll 2
    for (int k4 = 0; k4 < D2/4; k4++) {
        // 4 consecutive k's of column d: W2q[k4*1024 + d*4 .. +3]
        ulonglong2 wq = *reinterpret_cast<const ulonglong2*>(g_W2q + k4*1024 + d*4);
        #pragma unroll
        for (int r = 0; r < 16; r++) {
            ulonglong2 hq = *reinterpret_cast<const ulonglong2*>(sbuf + r*D2 + k4*4);
            ffma2(acc[r], hq.x, wq.x);
            ffma2(acc[r], hq.y, wq.y);
        }
    }
    __syncthreads();   // done reading H tile; reuse sbuf for x

    float bbias = b2[d];
    #pragma unroll
    for (int r = 0; r < 16; r++) {
        float2 a = unpack2(acc[r]);
        sbuf[r*DD + d] = pos_emb[(s0 + r)*DD + d] + (a.x + a.y) + scnt[r]*bbias;
    }
    __syncthreads();

    // layernorm: warp w handles rows 2w, 2w+1 (8 warps x 2 rows = 16)
    int warp = d >> 5, lane = d & 31;
    #pragma unroll
    for (int rr = 0; rr < 2; rr++) {
        int r = warp*2 + rr;
        float v[8];
        float sum = 0.f;
        #pragma unroll
        for (int q = 0; q < 8; q++) {
            v[q] = sbuf[r*DD + lane + q*32];
            sum += v[q];
        }
        #pragma unroll
        for (int o = 16; o > 0; o >>= 1) sum += __shfl_xor_sync(0xffffffffu, sum, o);
        float mu = sum * (1.f/DD);
        float sq = 0.f;
        #pragma unroll
        for (int q = 0; q < 8; q++) { float tq = v[q] - mu; sq += tq*tq; }
        #pragma unroll
        for (int o = 16; o > 0; o >>= 1) sq += __shfl_xor_sync(0xffffffffu, sq, o);
        float rstd = rsqrtf(sq * (1.f/DD) + 1e-5f);
        #pragma unroll
        for (int q = 0; q < 8; q++) {
            int dd = lane + q*32;
            sbuf[r*DD + dd] = (v[q] - mu) * rstd * ln_g[dd] + ln_b[dd];
        }
    }
    __syncthreads();

    // partial pooled sum over the 16 rows, one atomic per (b,d) per block
    float ps = 0.f;
    #pragma unroll
    for (int r = 0; r < 16; r++) ps += sbuf[r*DD + d];
    atomicAdd(&g_pool[b*DD + d], ps);
}

// ---------------- 4: final MLP, split-K across the chip ---------------------
// F1: grid (BB, 8) — k-slice of 32; 512 threads = column j.
__global__ __launch_bounds__(512) void final1_kernel(
    const float* __restrict__ Wl1)
{
    __shared__ float sp[32];
    int b  = blockIdx.x;
    int k0 = blockIdx.y * 32;
    int j  = threadIdx.x;
    if (j < 32) sp[j] = g_pool[b*DD + k0 + j] * (1.f / SS);   // pooled mean slice
    __syncthreads();
    float acc = 0.f;
    #pragma unroll
    for (int k = 0; k < 32; k++)
        acc = fmaf(sp[k], Wl1[(size_t)(k0 + k)*DLAT + j], acc);
    atomicAdd(&g_L1raw[b*DLAT + j], acc);
}

// F2: bias + gelu; also initialize out with bl2 (out is poisoned pre-timing).
__global__ __launch_bounds__(512) void final_mid_kernel(
    const float* __restrict__ bl1, const float* __restrict__ bl2,
    float* __restrict__ out)
{
    int b = blockIdx.x, j = threadIdx.x;
    g_L1[b*DLAT + j] = gelu_f(g_L1raw[b*DLAT + j] + bl1[j]);
    out[b*DLAT + j]  = bl2[j];
}

// F3: grid (BB, 8) — k-slice of 64; 512 threads = column j; accumulate into out.
__global__ __launch_bounds__(512) void final2_kernel(
    const float* __restrict__ Wl2, float* __restrict__ out)
{
    __shared__ float sl[64];
    int b  = blockIdx.x;
    int k0 = blockIdx.y * 64;
    int j  = threadIdx.x;
    if (j < 64) sl[j] = g_L1[b*DLAT + k0 + j];
    __syncthreads();
    float acc = 0.f;
    #pragma unroll
    for (int k = 0; k < 64; k++)
        acc = fmaf(sl[k], Wl2[(size_t)(k0 + k)*DLAT + j], acc);
    atomicAdd(&out[b*DLAT + j], acc);
}

// ---------------- launch ----------------------------------------------------
extern "C" void kernel_launch(void* const* d_in, const int* in_sizes, int n_in,
                              void* d_out, int out_size)
{
    const int*   a0       = (const int*)  d_in[0];
    const int*   a1       = (const int*)  d_in[1];
    const int*   pred_idx = (const int*)  d_in[2];
    const int*   role_idx = (const int*)  d_in[3];
    // d_in[4] = seq_len (compile-time SS)
    const float* pos_emb  = (const float*)d_in[5];
    const float* pred_emb = (const float*)d_in[6];
    const float* role_emb = (const float*)d_in[7];
    const float* W1       = (const float*)d_in[8];
    const float* b1       = (const float*)d_in[9];
    const float* W2       = (const float*)d_in[10];
    const float* b2       = (const float*)d_in[11];
    const float* ln_g     = (const float*)d_in[12];
    const float* ln_b     = (const float*)d_in[13];
    const float* Wl1      = (const float*)d_in[14];
    const float* bl1      = (const float*)d_in[15];
    const float* Wl2      = (const float*)d_in[16];
    const float* bl2      = (const float*)d_in[17];
    float* out = (float*)d_out;

    prep_kernel<<<512, 256>>>(pos_emb, pred_emb, role_emb, W1, b1, W2);
    bin_kernel<<<NEDGE/256, 256>>>(a0, a1, pred_idx, role_idx);
    accum_kernel<<<BB*SS, 128>>>(a0, a1, pred_idx, role_idx);
    dim3 ngrid(SS/16, BB);
    node_kernel<<<ngrid, 256>>>(pos_emb, b2, ln_g, ln_b);
    dim3 f1grid(BB, 8);
    final1_kernel<<<f1grid, DLAT>>>(Wl1);
    final_mid_kernel<<<BB, DLAT>>>(bl1, bl2, out);
    dim3 f2grid(BB, 8);
    final2_kernel<<<f2grid, DLAT>>>(Wl2, out);
}

// round 9
// speedup vs baseline: 1.3230x; 1.3230x over previous
#include <cuda_runtime.h>
#include <math.h>

// Problem constants (B, F, S, D) = (16, 2048, 512, 256)
#define BB   16
#define FF   2048
#define SS   512
#define DD   256
#define D2   512    // 2*D (hidden width of edge MLP, width of H rows)
#define DLAT 512

#define NEDGE (BB*FF)

typedef unsigned long long ull;

// ---------------- scratch (device globals; no allocation allowed) ----------
__device__ float g_NA[SS*D2];     // nodes @ W1[0:256]        (1 MB)
__device__ float g_NC[SS*D2];     // nodes @ W1[512:768]      (1 MB)
__device__ float g_PP[8*D2];      // pred_emb @ W1[256:512] + b1
__device__ float g_RC[8*D2];      // role_emb @ W1[512:768]
__device__ float g_H [BB*SS*D2];  // segment-summed gelu(pre) (16 MB)
__device__ float g_cnt[BB*SS];    // message counts per (b,node)
__device__ float g_pool[BB*DD];   // sum over S of layernormed x
__device__ float g_L1raw[BB*DLAT];// split-K partial sums of pooled@Wl1
__device__ float g_L1[BB*DLAT];   // gelu(pooled@Wl1+bl1)

__device__ __forceinline__ float gelu_f(float x) {
    return 0.5f * x * (1.0f + erff(x * 0.70710678118654752f));
}

// packed f32x2 fma: d = a*b + d  (elementwise on the two packed floats)
__device__ __forceinline__ void ffma2(ull& d, ull a, ull b) {
    asm("fma.rn.f32x2 %0, %1, %2, %3;" : "=l"(d) : "l"(a), "l"(b), "l"(d));
}
__device__ __forceinline__ ull pack2(float x, float y) {
    ull r; asm("mov.b64 %0, {%1, %2};" : "=l"(r) : "f"(x), "f"(y)); return r;
}
__device__ __forceinline__ float2 unpack2(ull v) {
    float2 r; asm("mov.b64 {%0, %1}, %2;" : "=f"(r.x), "=f"(r.y) : "l"(v)); return r;
}
// 128-bit vector reduction (sm_90+)
__device__ __forceinline__ void red_add_v4(float* addr, float4 v) {
    asm volatile("red.global.add.v4.f32 [%0], {%1, %2, %3, %4};"
                 :: "l"(addr), "f"(v.x), "f"(v.y), "f"(v.z), "f"(v.w) : "memory");
}

// ---------------- 0: zero the big H accumulator ------------------------------
__global__ void zeroH_kernel() {
    int idx    = blockIdx.x * blockDim.x + threadIdx.x;
    int stride = gridDim.x * blockDim.x;
    float4 z = make_float4(0.f, 0.f, 0.f, 0.f);
    for (int i = idx; i < (BB*SS*D2)/4; i += stride)
        reinterpret_cast<float4*>(g_H)[i] = z;
}

// ---------------- 1: merged prep kernel ------------------------------------
// grid = 256 blocks x 256 threads; block roles:
//   [0,64):    NA/NC precompute (8 node rows each, f32x2)
//   [64,80):   PP (rows 0-7) / RC (rows 8-15)
//   [80,256):  zero g_cnt, g_pool, g_L1raw
__global__ __launch_bounds__(256) void prep_kernel(
    const float* __restrict__ pos_emb, const float* __restrict__ pred_emb,
    const float* __restrict__ role_emb, const float* __restrict__ W1,
    const float* __restrict__ b1)
{
    __shared__ float sh[8*DD];
    int bid = blockIdx.x;
    int tid = threadIdx.x;

    if (bid < 64) {
        // ---- NA = nodes@W1a, NC = nodes@W1c, rows [bid*8, bid*8+8) ----
        int r0 = bid * 8;
        #pragma unroll
        for (int r = 0; r < 8; r++)
            sh[r*DD + tid] = pos_emb[(r0 + r)*DD + tid];
        __syncthreads();

        ull aA[8], aC[8];
        #pragma unroll
        for (int r = 0; r < 8; r++) { aA[r] = 0ull; aC[r] = 0ull; }
        int j2 = 2*tid;   // column pair (2*tid, 2*tid+1)
        #pragma unroll 2
        for (int k = 0; k < DD; k++) {
            ull wa = *reinterpret_cast<const ull*>(W1 + (size_t)k*D2 + j2);
            ull wc = *reinterpret_cast<const ull*>(W1 + (size_t)(512 + k)*D2 + j2);
            #pragma unroll
            for (int r = 0; r < 8; r++) {
                float h = sh[r*DD + k];
                ull hp = pack2(h, h);
                ffma2(aA[r], hp, wa);
                ffma2(aC[r], hp, wc);
            }
        }
        #pragma unroll
        for (int r = 0; r < 8; r++) {
            *reinterpret_cast<ull*>(g_NA + (r0+r)*D2 + j2) = aA[r];
            *reinterpret_cast<ull*>(g_NC + (r0+r)*D2 + j2) = aC[r];
        }
    } else if (bid < 80) {
        // ---- PP = pred_emb@W1p + b1 (rows 0-7), RC = role_emb@W1c (8-15) ----
        int row = bid - 64;
        bool is_pred = (row < 8);
        const float* src = is_pred ? (pred_emb + row*DD) : (role_emb + (row-8)*DD);
        sh[tid] = src[tid];
        __syncthreads();

        const float* Wbase = is_pred ? (W1 + 256*D2) : (W1 + 512*D2);
        ull acc = 0ull;
        int j2 = 2*tid;
        #pragma unroll 4
        for (int k = 0; k < DD; k++) {
            ull w = *reinterpret_cast<const ull*>(Wbase + (size_t)k*D2 + j2);
            float s = sh[k];
            ffma2(acc, pack2(s, s), w);
        }
        float2 a = unpack2(acc);
        if (is_pred) {
            g_PP[row*D2 + j2    ] = a.x + b1[j2];
            g_PP[row*D2 + j2 + 1] = a.y + b1[j2+1];
        } else {
            g_RC[(row-8)*D2 + j2    ] = a.x;
            g_RC[(row-8)*D2 + j2 + 1] = a.y;
        }
    } else {
        // ---- zero small accumulators ----
        int idx    = (bid - 80)*256 + tid;
        int stride = (256 - 80)*256;
        float4 z = make_float4(0.f, 0.f, 0.f, 0.f);
        for (int i = idx; i < (BB*SS)/4;    i += stride) reinterpret_cast<float4*>(g_cnt)[i]    = z;
        for (int i = idx; i < (BB*DD)/4;    i += stride) reinterpret_cast<float4*>(g_pool)[i]   = z;
        for (int i = idx; i < (BB*DLAT)/4;  i += stride) reinterpret_cast<float4*>(g_L1raw)[i]  = z;
    }
}

// ---------------- 2: edge kernel (round-6 RED version) ----------------------
// 128 threads, 4 edges per block; thread j handles 4 contiguous floats.
__global__ __launch_bounds__(128) void edge_kernel(
    const int* __restrict__ a0, const int* __restrict__ a1,
    const int* __restrict__ pred, const int* __restrict__ role)
{
    int j  = threadIdx.x;              // 0..127
    int e0 = blockIdx.x * 4;

    #pragma unroll
    for (int t = 0; t < 4; t++) {
        int e = e0 + t;
        int b = e >> 11;                  // / FF
        int i0 = __ldg(&a0[e]);
        int i1 = __ldg(&a1[e]);
        int p  = __ldg(&pred[e]);
        bool is_role = (p == 1);
        bool do_bwd  = (p >= 2);

        const float4* na0 = reinterpret_cast<const float4*>(g_NA + i0*D2);
        const float4* pp  = reinterpret_cast<const float4*>(g_PP + p *D2);
        const float4* thirdp = is_role
            ? reinterpret_cast<const float4*>(g_RC + (__ldg(&role[e]) + 1)*D2)
            : reinterpret_cast<const float4*>(g_NC + i1*D2);
        int dst = is_role ? i0 : i1;
        float* Hf = g_H + (size_t)(b*SS + dst)*D2;

        float4 va = na0[j];
        float4 vp = pp[j];
        float4 vt = thirdp[j];
        float4 g;
        g.x = gelu_f(va.x + vp.x + vt.x);
        g.y = gelu_f(va.y + vp.y + vt.y);
        g.z = gelu_f(va.z + vp.z + vt.z);
        g.w = gelu_f(va.w + vp.w + vt.w);
        red_add_v4(Hf + 4*j, g);

        if (do_bwd) {
            const float4* na1 = reinterpret_cast<const float4*>(g_NA + i1*D2);
            const float4* nc0 = reinterpret_cast<const float4*>(g_NC + i0*D2);
            float* Hb = g_H + (size_t)(b*SS + i0)*D2;
            float4 vb = na1[j];
            float4 vc = nc0[j];
            float4 h;
            h.x = gelu_f(vb.x + vp.x + vc.x);
            h.y = gelu_f(vb.y + vp.y + vc.y);
            h.z = gelu_f(vb.z + vp.z + vc.z);
            h.w = gelu_f(vb.w + vp.w + vc.w);
            red_add_v4(Hb + 4*j, h);
        }
        if (j == 0) {
            atomicAdd(&g_cnt[b*SS + dst], 1.0f);
            if (do_bwd) atomicAdd(&g_cnt[b*SS + i0], 1.0f);
        }
    }
}

// ---------------- 3: node kernel (register-tiled 4x4 GEMM) ------------------
// grid (SS/16, BB), 256 threads; block = 16 rows x 256 cols.
// Thread tile: 4 rows x 4 cols.  acc = f32x2 over COLUMN pairs, so W2's
// row-major float4 loads are already packed operands (zero pack cost).
__global__ __launch_bounds__(256) void node_kernel(
    const float* __restrict__ pos_emb, const float* __restrict__ W2,
    const float* __restrict__ b2, const float* __restrict__ ln_g,
    const float* __restrict__ ln_b)
{
    __shared__ float sbuf[16 * D2];   // 32 KB: phase1 = H tile, phase2 = x rows
    __shared__ float scnt[16];

    int b   = blockIdx.y;
    int s0  = blockIdx.x * 16;
    int tid = threadIdx.x;            // 0..255

    // load H tile [16][512] = 2048 float4, 8 per thread
    {
        const float4* Hv = reinterpret_cast<const float4*>(g_H + (size_t)(b*SS + s0)*D2);
        float4* sv = reinterpret_cast<float4*>(sbuf);
        #pragma unroll
        for (int i = 0; i < 8; i++) sv[tid + i*256] = Hv[tid + i*256];
    }
    if (tid < 16) scnt[tid] = g_cnt[b*SS + s0 + tid];
    __syncthreads();

    int c0 = (tid & 63) * 4;          // column group (4 cols)
    int r0 = (tid >> 6) * 4;          // row group   (4 rows)

    // acc[r][p] = f32x2 sums for cols (c0+2p, c0+2p+1) of row r0+r
    ull acc[4][2];
    #pragma unroll
    for (int r = 0; r < 4; r++) { acc[r][0] = 0ull; acc[r][1] = 0ull; }

    #pragma unroll 2
    for (int k4 = 0; k4 < D2/4; k4++) {
        // w rows k4*4..+3, cols c0..c0+3: float4 == 2 packed f32x2 col-pairs
        const float* wbase = W2 + (size_t)(k4*4)*DD + c0;
        ulonglong2 w0 = *reinterpret_cast<const ulonglong2*>(wbase);
        ulonglong2 w1 = *reinterpret_cast<const ulonglong2*>(wbase + DD);
        ulonglong2 w2v = *reinterpret_cast<const ulonglong2*>(wbase + 2*DD);
        ulonglong2 w3 = *reinterpret_cast<const ulonglong2*>(wbase + 3*DD);
        #pragma unroll
        for (int r = 0; r < 4; r++) {
            float4 h = *reinterpret_cast<const float4*>(sbuf + (r0+r)*D2 + k4*4);
            ull hx = pack2(h.x, h.x);
            ull hy = pack2(h.y, h.y);
            ull hz = pack2(h.z, h.z);
            ull hw = pack2(h.w, h.w);
            ffma2(acc[r][0], hx, w0.x); ffma2(acc[r][1], hx, w0.y);
            ffma2(acc[r][0], hy, w1.x); ffma2(acc[r][1], hy, w1.y);
            ffma2(acc[r][0], hz, w2v.x); ffma2(acc[r][1], hz, w2v.y);
            ffma2(acc[r][0], hw, w3.x); ffma2(acc[r][1], hw, w3.y);
        }
    }
    __syncthreads();   // done reading H tile; reuse sbuf for x

    // x = pos_emb + agg + cnt*b2  (each thread writes its 4x4 tile)
    {
        float4 bb = *reinterpret_cast<const float4*>(b2 + c0);
        #pragma unroll
        for (int r = 0; r < 4; r++) {
            int row = s0 + r0 + r;
            float4 pe = *reinterpret_cast<const float4*>(pos_emb + (size_t)row*DD + c0);
            float cn = scnt[r0 + r];
            float2 p0 = unpack2(acc[r][0]);
            float2 p1 = unpack2(acc[r][1]);
            float4 xv;
            xv.x = pe.x + p0.x + cn*bb.x;
            xv.y = pe.y + p0.y + cn*bb.y;
            xv.z = pe.z + p1.x + cn*bb.z;
            xv.w = pe.w + p1.y + cn*bb.w;
            *reinterpret_cast<float4*>(sbuf + (r0+r)*DD + c0) = xv;
        }
    }
    __syncthreads();

    // layernorm: warp w handles rows 2w, 2w+1 (8 warps x 2 rows = 16)
    int warp = tid >> 5, lane = tid & 31;
    #pragma unroll
    for (int rr = 0; rr < 2; rr++) {
        int r = warp*2 + rr;
        float v[8];
        float sum = 0.f;
        #pragma unroll
        for (int q = 0; q < 8; q++) {
            v[q] = sbuf[r*DD + lane + q*32];
            sum += v[q];
        }
        #pragma unroll
        for (int o = 16; o > 0; o >>= 1) sum += __shfl_xor_sync(0xffffffffu, sum, o);
        float mu = sum * (1.f/DD);
        float sq = 0.f;
        #pragma unroll
        for (int q = 0; q < 8; q++) { float tq = v[q] - mu; sq += tq*tq; }
        #pragma unroll
        for (int o = 16; o > 0; o >>= 1) sq += __shfl_xor_sync(0xffffffffu, sq, o);
        float rstd = rsqrtf(sq * (1.f/DD) + 1e-5f);
        #pragma unroll
        for (int q = 0; q < 8; q++) {
            int dd = lane + q*32;
            sbuf[r*DD + dd] = (v[q] - mu) * rstd * ln_g[dd] + ln_b[dd];
        }
    }
    __syncthreads();

    // partial pooled sum over the 16 rows, one atomic per (b,d) per block
    float ps = 0.f;
    #pragma unroll
    for (int r = 0; r < 16; r++) ps += sbuf[r*DD + tid];
    atomicAdd(&g_pool[b*DD + tid], ps);
}

// ---------------- 4: final MLP, split-K across the chip ---------------------
// F1: grid (BB, 8) — k-slice of 32; 512 threads = column j.
__global__ __launch_bounds__(512) void final1_kernel(
    const float* __restrict__ Wl1)
{
    __shared__ float sp[32];
    int b  = blockIdx.x;
    int k0 = blockIdx.y * 32;
    int j  = threadIdx.x;
    if (j < 32) sp[j] = g_pool[b*DD + k0 + j] * (1.f / SS);   // pooled mean slice
    __syncthreads();
    float acc = 0.f;
    #pragma unroll
    for (int k = 0; k < 32; k++)
        acc = fmaf(sp[k], Wl1[(size_t)(k0 + k)*DLAT + j], acc);
    atomicAdd(&g_L1raw[b*DLAT + j], acc);
}

// F2: bias + gelu; also initialize out with bl2 (out is poisoned pre-timing).
__global__ __launch_bounds__(512) void final_mid_kernel(
    const float* __restrict__ bl1, const float* __restrict__ bl2,
    float* __restrict__ out)
{
    int b = blockIdx.x, j = threadIdx.x;
    g_L1[b*DLAT + j] = gelu_f(g_L1raw[b*DLAT + j] + bl1[j]);
    out[b*DLAT + j]  = bl2[j];
}

// F3: grid (BB, 8) — k-slice of 64; 512 threads = column j; accumulate into out.
__global__ __launch_bounds__(512) void final2_kernel(
    const float* __restrict__ Wl2, float* __restrict__ out)
{
    __shared__ float sl[64];
    int b  = blockIdx.x;
    int k0 = blockIdx.y * 64;
    int j  = threadIdx.x;
    if (j < 64) sl[j] = g_L1[b*DLAT + k0 + j];
    __syncthreads();
    float acc = 0.f;
    #pragma unroll
    for (int k = 0; k < 64; k++)
        acc = fmaf(sl[k], Wl2[(size_t)(k0 + k)*DLAT + j], acc);
    atomicAdd(&out[b*DLAT + j], acc);
}

// ---------------- launch ----------------------------------------------------
extern "C" void kernel_launch(void* const* d_in, const int* in_sizes, int n_in,
                              void* d_out, int out_size)
{
    const int*   a0       = (const int*)  d_in[0];
    const int*   a1       = (const int*)  d_in[1];
    const int*   pred_idx = (const int*)  d_in[2];
    const int*   role_idx = (const int*)  d_in[3];
    // d_in[4] = seq_len (compile-time SS)
    const float* pos_emb  = (const float*)d_in[5];
    const float* pred_emb = (const float*)d_in[6];
    const float* role_emb = (const float*)d_in[7];
    const float* W1       = (const float*)d_in[8];
    const float* b1       = (const float*)d_in[9];
    const float* W2       = (const float*)d_in[10];
    const float* b2       = (const float*)d_in[11];
    const float* ln_g     = (const float*)d_in[12];
    const float* ln_b     = (const float*)d_in[13];
    const float* Wl1      = (const float*)d_in[14];
    const float* bl1      = (const float*)d_in[15];
    const float* Wl2      = (const float*)d_in[16];
    const float* bl2      = (const float*)d_in[17];
    float* out = (float*)d_out;

    zeroH_kernel<<<1024, 256>>>();                                   // launch 1
    prep_kernel<<<256, 256>>>(pos_emb, pred_emb, role_emb, W1, b1);  // launch 2
    edge_kernel<<<NEDGE/4, 128>>>(a0, a1, pred_idx, role_idx);       // launch 3
    dim3 ngrid(SS/16, BB);
    node_kernel<<<ngrid, 256>>>(pos_emb, W2, b2, ln_g, ln_b);        // launch 4 (profiled)
    dim3 f1grid(BB, 8);
    final1_kernel<<<f1grid, DLAT>>>(Wl1);
    final_mid_kernel<<<BB, DLAT>>>(bl1, bl2, out);
    dim3 f2grid(BB, 8);
    final2_kernel<<<f2grid, DLAT>>>(Wl2, out);
}